// round 1
// baseline (speedup 1.0000x reference)
#include <cuda_runtime.h>

#define BATCH 4
#define SEQ 2048
#define DIM 1024
#define HEADS 16
#define DHEAD 64
#define INNER 1024
#define ROWS (BATCH * SEQ)      /* 8192 */
#define QKV_COLS (3 * INNER)    /* 3072 */
#define ATT_SCALE 0.125f        /* 64^-0.5 */
#define APAD 68                 /* padded row length in attention smem tiles */

// Scratch (allocation-free rule: device globals)
__device__ float g_qkv[(size_t)ROWS * QKV_COLS];   // [8192, 3072]
__device__ float g_attn[(size_t)ROWS * INNER];     // [8192, 1024]

// ---------------------------------------------------------------------------
// Tiled fp32 GEMM with bias: C[M,N] = A[M,K] @ B[K,N] + bias[N]
// BM=BN=128, BK=8, 256 threads, 8x8 register tile per thread.
// Requires M%128==0, N%128==0, K%8==0 (true for all shapes here).
// ---------------------------------------------------------------------------
__global__ __launch_bounds__(256) void sgemm_bias(
    const float* __restrict__ A, const float* __restrict__ B,
    const float* __restrict__ bias, float* __restrict__ C,
    int M, int N, int K)
{
    const int BM = 128, BN = 128, BK = 8;
    __shared__ float As[BK][BM];   // transposed A tile
    __shared__ float Bs[BK][BN];

    const int tid = threadIdx.x;
    const int block_row = blockIdx.y * BM;
    const int block_col = blockIdx.x * BN;

    const int aRow = tid >> 1;          // 0..127
    const int aCol = (tid & 1) << 2;    // 0 or 4
    const int bRow = tid >> 5;          // 0..7
    const int bCol = (tid & 31) << 2;   // 0..124

    const int tr = (tid >> 4) << 3;     // thread row base (0..120)
    const int tc = (tid & 15) << 3;     // thread col base (0..120)

    const float* Ap = A + (size_t)(block_row + aRow) * K + aCol;
    const float* Bp = B + (size_t)bRow * N + block_col + bCol;

    float acc[8][8] = {};
    float ra[8], rb[8];

    for (int k0 = 0; k0 < K; k0 += BK) {
        float4 av = *(const float4*)(Ap + k0);
        As[aCol + 0][aRow] = av.x;
        As[aCol + 1][aRow] = av.y;
        As[aCol + 2][aRow] = av.z;
        As[aCol + 3][aRow] = av.w;
        *(float4*)&Bs[bRow][bCol] = *(const float4*)(Bp + (size_t)k0 * N);
        __syncthreads();

        #pragma unroll
        for (int k = 0; k < BK; k++) {
            *(float4*)&ra[0] = *(const float4*)&As[k][tr];
            *(float4*)&ra[4] = *(const float4*)&As[k][tr + 4];
            *(float4*)&rb[0] = *(const float4*)&Bs[k][tc];
            *(float4*)&rb[4] = *(const float4*)&Bs[k][tc + 4];
            #pragma unroll
            for (int i = 0; i < 8; i++)
                #pragma unroll
                for (int j = 0; j < 8; j++)
                    acc[i][j] += ra[i] * rb[j];
        }
        __syncthreads();
    }

    #pragma unroll
    for (int i = 0; i < 8; i++) {
        float* Cp = C + (size_t)(block_row + tr + i) * N + block_col + tc;
        #pragma unroll
        for (int j = 0; j < 8; j += 4) {
            float4 o;
            o.x = acc[i][j + 0] + bias[block_col + tc + j + 0];
            o.y = acc[i][j + 1] + bias[block_col + tc + j + 1];
            o.z = acc[i][j + 2] + bias[block_col + tc + j + 2];
            o.w = acc[i][j + 3] + bias[block_col + tc + j + 3];
            *(float4*)(Cp + j) = o;
        }
    }
}

// ---------------------------------------------------------------------------
// Flash attention: one block per (q-tile of 64, head, batch).
// 256 threads as 16x16; each thread owns a 4(row) x 4(col) fragment.
// Online softmax, O accumulated in registers.
// smem: Qt[64][APAD] (dim-major), KV[64][APAD] (K dim-major / V key-major), Ps[64][APAD]
// ---------------------------------------------------------------------------
__global__ __launch_bounds__(256) void attn_kernel(float* __restrict__ attn_out)
{
    extern __shared__ float sm[];
    float* Qt = sm;                  // Qt[d*APAD + r], pre-scaled by ATT_SCALE
    float* KV = sm + 64 * APAD;      // K phase: Kt[d*APAD + c]; V phase: Vs[k*APAD + d]
    float* Ps = sm + 2 * 64 * APAD;  // Ps[r*APAD + k]

    const int tid = threadIdx.x;
    const int tx = tid & 15;
    const int ty = tid >> 4;
    const int qtile = blockIdx.x;
    const int h = blockIdx.y;
    const int b = blockIdx.z;

    const float* qbase = g_qkv + (size_t)b * SEQ * QKV_COLS + h * DHEAD;
    const float* kbase = qbase + INNER;
    const float* vbase = qbase + 2 * INNER;

    // Load Q tile (64 rows x 64 dims), transposed into smem, pre-scaled.
    #pragma unroll
    for (int it = 0; it < 4; it++) {
        int i = tid + it * 256;
        int row = i >> 4;
        int d4 = (i & 15) << 2;
        float4 v = *(const float4*)(qbase + (size_t)(qtile * 64 + row) * QKV_COLS + d4);
        Qt[(d4 + 0) * APAD + row] = v.x * ATT_SCALE;
        Qt[(d4 + 1) * APAD + row] = v.y * ATT_SCALE;
        Qt[(d4 + 2) * APAD + row] = v.z * ATT_SCALE;
        Qt[(d4 + 3) * APAD + row] = v.w * ATT_SCALE;
    }

    float O[4][4] = {};
    float m[4] = {-1e30f, -1e30f, -1e30f, -1e30f};
    float l[4] = {};

    for (int t = 0; t < SEQ / 64; t++) {
        // Load K tile (64 keys x 64 dims), transposed (dim-major).
        #pragma unroll
        for (int it = 0; it < 4; it++) {
            int i = tid + it * 256;
            int col = i >> 4;
            int d4 = (i & 15) << 2;
            float4 v = *(const float4*)(kbase + (size_t)(t * 64 + col) * QKV_COLS + d4);
            KV[(d4 + 0) * APAD + col] = v.x;
            KV[(d4 + 1) * APAD + col] = v.y;
            KV[(d4 + 2) * APAD + col] = v.z;
            KV[(d4 + 3) * APAD + col] = v.w;
        }
        __syncthreads();   // K visible (and Q on first iter)

        // S = Q K^T fragment (4x4)
        float s00 = 0.f, s01 = 0.f, s02 = 0.f, s03 = 0.f;
        float s10 = 0.f, s11 = 0.f, s12 = 0.f, s13 = 0.f;
        float s20 = 0.f, s21 = 0.f, s22 = 0.f, s23 = 0.f;
        float s30 = 0.f, s31 = 0.f, s32 = 0.f, s33 = 0.f;
        #pragma unroll 8
        for (int d = 0; d < 64; d++) {
            float4 a = *(const float4*)&Qt[d * APAD + ty * 4];
            float4 bb = *(const float4*)&KV[d * APAD + tx * 4];
            s00 += a.x * bb.x; s01 += a.x * bb.y; s02 += a.x * bb.z; s03 += a.x * bb.w;
            s10 += a.y * bb.x; s11 += a.y * bb.y; s12 += a.y * bb.z; s13 += a.y * bb.w;
            s20 += a.z * bb.x; s21 += a.z * bb.y; s22 += a.z * bb.z; s23 += a.z * bb.w;
            s30 += a.w * bb.x; s31 += a.w * bb.y; s32 += a.w * bb.z; s33 += a.w * bb.w;
        }
        __syncthreads();   // done reading K; KV buffer may be overwritten

        // Load V tile (key-major) into KV buffer.
        #pragma unroll
        for (int it = 0; it < 4; it++) {
            int i = tid + it * 256;
            int kk = i >> 4;
            int d4 = (i & 15) << 2;
            *(float4*)&KV[kk * APAD + d4] =
                *(const float4*)(vbase + (size_t)(t * 64 + kk) * QKV_COLS + d4);
        }

        // Online softmax per owned row (4 rows); row group = 16 lanes (same ty).
        float sr[4][4] = {
            {s00, s01, s02, s03}, {s10, s11, s12, s13},
            {s20, s21, s22, s23}, {s30, s31, s32, s33}};
        #pragma unroll
        for (int i = 0; i < 4; i++) {
            float tmax = fmaxf(fmaxf(sr[i][0], sr[i][1]), fmaxf(sr[i][2], sr[i][3]));
            tmax = fmaxf(tmax, __shfl_xor_sync(0xffffffffu, tmax, 8));
            tmax = fmaxf(tmax, __shfl_xor_sync(0xffffffffu, tmax, 4));
            tmax = fmaxf(tmax, __shfl_xor_sync(0xffffffffu, tmax, 2));
            tmax = fmaxf(tmax, __shfl_xor_sync(0xffffffffu, tmax, 1));
            float mn = fmaxf(m[i], tmax);
            float corr = __expf(m[i] - mn);
            m[i] = mn;
            float p0 = __expf(sr[i][0] - mn);
            float p1 = __expf(sr[i][1] - mn);
            float p2 = __expf(sr[i][2] - mn);
            float p3 = __expf(sr[i][3] - mn);
            float ls = p0 + p1 + p2 + p3;
            ls += __shfl_xor_sync(0xffffffffu, ls, 8);
            ls += __shfl_xor_sync(0xffffffffu, ls, 4);
            ls += __shfl_xor_sync(0xffffffffu, ls, 2);
            ls += __shfl_xor_sync(0xffffffffu, ls, 1);
            l[i] = l[i] * corr + ls;
            O[i][0] *= corr; O[i][1] *= corr; O[i][2] *= corr; O[i][3] *= corr;
            float4 pv = make_float4(p0, p1, p2, p3);
            *(float4*)&Ps[(ty * 4 + i) * APAD + tx * 4] = pv;
        }
        __syncthreads();   // V + P visible

        // O += P @ V
        #pragma unroll 4
        for (int kk = 0; kk < 64; kk++) {
            float4 vv = *(const float4*)&KV[kk * APAD + tx * 4];
            #pragma unroll
            for (int i = 0; i < 4; i++) {
                float p = Ps[(ty * 4 + i) * APAD + kk];
                O[i][0] += p * vv.x;
                O[i][1] += p * vv.y;
                O[i][2] += p * vv.z;
                O[i][3] += p * vv.w;
            }
        }
        __syncthreads();   // done reading V/P before next K load
    }

    // Write normalized O: attn layout b n (h d) -> [8192, 1024]
    #pragma unroll
    for (int i = 0; i < 4; i++) {
        float inv = 1.0f / l[i];
        float4 o = make_float4(O[i][0] * inv, O[i][1] * inv, O[i][2] * inv, O[i][3] * inv);
        size_t row = (size_t)b * SEQ + qtile * 64 + ty * 4 + i;
        *(float4*)(attn_out + row * INNER + h * DHEAD + tx * 4) = o;
    }
}

// ---------------------------------------------------------------------------
extern "C" void kernel_launch(void* const* d_in, const int* in_sizes, int n_in,
                              void* d_out, int out_size)
{
    const float* x     = (const float*)d_in[0];
    const float* w_qkv = (const float*)d_in[1];
    const float* b_qkv = (const float*)d_in[2];
    const float* w_out = (const float*)d_in[3];
    const float* b_out = (const float*)d_in[4];
    float* out = (float*)d_out;

    float* qkv = nullptr;
    float* attn = nullptr;
    cudaGetSymbolAddress((void**)&qkv, g_qkv);
    cudaGetSymbolAddress((void**)&attn, g_attn);

    const int attn_smem = 3 * 64 * APAD * (int)sizeof(float);  // 52224 B
    cudaFuncSetAttribute(attn_kernel, cudaFuncAttributeMaxDynamicSharedMemorySize, attn_smem);

    // 1) qkv = x @ w_qkv + b_qkv
    sgemm_bias<<<dim3(QKV_COLS / 128, ROWS / 128), 256>>>(
        x, w_qkv, b_qkv, qkv, ROWS, QKV_COLS, DIM);

    // 2) flash attention -> g_attn  [b n (h d)]
    attn_kernel<<<dim3(SEQ / 64, HEADS, BATCH), 256, attn_smem>>>(attn);

    // 3) out = attn @ w_out + b_out
    sgemm_bias<<<dim3(DIM / 128, ROWS / 128), 256>>>(
        attn, w_out, b_out, out, ROWS, DIM, INNER);
}

// round 2
// speedup vs baseline: 1.3126x; 1.3126x over previous
#include <cuda_runtime.h>
#include <cuda_bf16.h>
#include <cstdint>

#define BATCH 4
#define SEQ 2048
#define DIM 1024
#define HEADS 16
#define DHEAD 64
#define INNER 1024
#define ROWS (BATCH * SEQ)      /* 8192 */
#define QKV_COLS (3 * INNER)    /* 3072 */
#define ATT_SCALE 0.125f
#define APAD 68

// ---------------- scratch (device globals; no allocation allowed) ----------
__device__ float g_qkv[(size_t)ROWS * QKV_COLS];   // [8192, 3072] fp32
__device__ float g_attn[(size_t)ROWS * INNER];     // [8192, 1024] fp32

__device__ __nv_bfloat16 g_xh[(size_t)ROWS * DIM];
__device__ __nv_bfloat16 g_xl[(size_t)ROWS * DIM];
__device__ __nv_bfloat16 g_ath[(size_t)ROWS * INNER];
__device__ __nv_bfloat16 g_atl[(size_t)ROWS * INNER];
__device__ __nv_bfloat16 g_wqkvh[(size_t)QKV_COLS * DIM];  // [N][K] transposed
__device__ __nv_bfloat16 g_wqkvl[(size_t)QKV_COLS * DIM];
__device__ __nv_bfloat16 g_wouth[(size_t)DIM * INNER];     // [N][K] transposed
__device__ __nv_bfloat16 g_woutl[(size_t)DIM * INNER];

// ---------------------------------------------------------------------------
// Split fp32 -> bf16 hi + bf16 lo (residual). 4 elems/thread.
// ---------------------------------------------------------------------------
__global__ void split_f32(const float* __restrict__ in,
                          __nv_bfloat16* __restrict__ hi,
                          __nv_bfloat16* __restrict__ lo, int n4)
{
    int i = blockIdx.x * blockDim.x + threadIdx.x;
    if (i >= n4) return;
    float4 v = ((const float4*)in)[i];
    float f[4] = {v.x, v.y, v.z, v.w};
    unsigned short hs[4], ls[4];
#pragma unroll
    for (int j = 0; j < 4; j++) {
        __nv_bfloat16 h = __float2bfloat16(f[j]);
        __nv_bfloat16 l = __float2bfloat16(f[j] - __bfloat162float(h));
        hs[j] = __bfloat16_as_ushort(h);
        ls[j] = __bfloat16_as_ushort(l);
    }
    uint2 uh = make_uint2((uint32_t)hs[0] | ((uint32_t)hs[1] << 16),
                          (uint32_t)hs[2] | ((uint32_t)hs[3] << 16));
    uint2 ul = make_uint2((uint32_t)ls[0] | ((uint32_t)ls[1] << 16),
                          (uint32_t)ls[2] | ((uint32_t)ls[3] << 16));
    ((uint2*)hi)[i] = uh;
    ((uint2*)lo)[i] = ul;
}

// ---------------------------------------------------------------------------
// Transpose + split: W[K][N] fp32 -> Th/Tl[N][K] bf16. 32x32 tiles.
// blockDim (32,8), grid (N/32, K/32)
// ---------------------------------------------------------------------------
__global__ void transpose_split(const float* __restrict__ W,
                                __nv_bfloat16* __restrict__ Th,
                                __nv_bfloat16* __restrict__ Tl, int K, int N)
{
    __shared__ float t[32][33];
    int k0 = blockIdx.y * 32, n0 = blockIdx.x * 32;
    int tx = threadIdx.x, ty = threadIdx.y;
#pragma unroll
    for (int j = 0; j < 4; j++)
        t[ty + j * 8][tx] = W[(size_t)(k0 + ty + j * 8) * N + n0 + tx];
    __syncthreads();
#pragma unroll
    for (int j = 0; j < 4; j++) {
        float f = t[tx][ty + j * 8];          // = W[k0+tx][n0+ty+8j]
        __nv_bfloat16 h = __float2bfloat16(f);
        __nv_bfloat16 l = __float2bfloat16(f - __bfloat162float(h));
        size_t o = (size_t)(n0 + ty + j * 8) * K + k0 + tx;
        Th[o] = h;
        Tl[o] = l;
    }
}

// ---------------------------------------------------------------------------
// bf16x3 tensor-core GEMM: C[M,N] = (Ah+Al)[M,K] @ (Bh+Bl)^T ([N][K]) + bias
// via AhBh + AhBl + AlBh. fp32 accum. BM=BN=128, BK=32, 256 thr (8 warps).
// Warp tile 32(M) x 64(N): 2 m16-tiles x 8 n8-tiles, mma.m16n8k16.bf16.
// cp.async double-buffered smem, padded rows (KP=40 bf16) => conflict-free LDSM.
// ---------------------------------------------------------------------------
#define GBM 128
#define GBN 128
#define GBK 32
#define GKP 40
#define GSTAGE (4 * GBM * GKP)  /* bf16 elems per stage: Ah,Al,Bh,Bl */
#define GSMEM (2 * GSTAGE * 2)  /* bytes, 2 stages */

#define LDSM4(r0, r1, r2, r3, addr)                                          \
    asm volatile("ldmatrix.sync.aligned.m8n8.x4.shared.b16 {%0,%1,%2,%3}, [%4];" \
                 : "=r"(r0), "=r"(r1), "=r"(r2), "=r"(r3) : "r"(addr))

#define MMA16816(d, a, b)                                                    \
    asm volatile("mma.sync.aligned.m16n8k16.row.col.f32.bf16.bf16.f32 "      \
                 "{%0,%1,%2,%3},{%4,%5,%6,%7},{%8,%9},{%0,%1,%2,%3};"        \
                 : "+f"(d[0]), "+f"(d[1]), "+f"(d[2]), "+f"(d[3])            \
                 : "r"(a[0]), "r"(a[1]), "r"(a[2]), "r"(a[3]),               \
                   "r"(b[0]), "r"(b[1]))

#define CPASYNC16(dst, src)                                                  \
    asm volatile("cp.async.cg.shared.global [%0], [%1], 16;" :: "r"(dst), "l"(src))

__global__ __launch_bounds__(256, 1) void gemm_bf16x3(
    const __nv_bfloat16* __restrict__ Ah, const __nv_bfloat16* __restrict__ Al,
    const __nv_bfloat16* __restrict__ Bh, const __nv_bfloat16* __restrict__ Bl,
    const float* __restrict__ bias, float* __restrict__ C,
    int M, int N, int K)
{
    extern __shared__ __nv_bfloat16 sm[];
    const int tid = threadIdx.x;
    const int lane = tid & 31, warp = tid >> 5;
    const int wm = warp >> 1, wn = warp & 1;     // 4 x 2 warp grid
    const int brow = blockIdx.y * GBM, bcol = blockIdx.x * GBN;

    uint32_t sbase = (uint32_t)__cvta_generic_to_shared(sm);

    // global->smem load mapping: id covers 128 rows x 4 k-chunks(8 bf16)
    const int lrow = tid >> 2;           // 0..63
    const int lk = (tid & 3) << 3;       // 0,8,16,24

    const __nv_bfloat16* gA[2] = {Ah, Al};
    const __nv_bfloat16* gB[2] = {Bh, Bl};

    float acc[2][8][4] = {};

    // ldmatrix per-thread offsets
    const int a_r = lane & 15;
    const int a_k = (lane >> 4) << 3;
    const int bg = lane >> 3;
    const int b_r = ((bg & 2) << 2) + (lane & 7);  // (bg>=2?8:0)+lane%8
    const int b_k = (bg & 1) << 3;

    const int NK = K / GBK;

    // ---- stage loader ----
    auto load_stage = [&](int st, int k0) {
        int base = st * GSTAGE;
#pragma unroll
        for (int v = 0; v < 2; v++) {
#pragma unroll
            for (int i = 0; i < 2; i++) {
                int row = lrow + i * 64;
                uint32_t da = sbase + (uint32_t)(base + v * GBM * GKP + row * GKP + lk) * 2;
                CPASYNC16(da, gA[v] + (size_t)(brow + row) * K + k0 + lk);
                uint32_t db = sbase + (uint32_t)(base + (2 + v) * GBM * GKP + row * GKP + lk) * 2;
                CPASYNC16(db, gB[v] + (size_t)(bcol + row) * K + k0 + lk);
            }
        }
    };

    load_stage(0, 0);
    asm volatile("cp.async.commit_group;");

    for (int kc = 0; kc < NK; kc++) {
        if (kc + 1 < NK) {
            load_stage((kc + 1) & 1, (kc + 1) * GBK);
            asm volatile("cp.async.commit_group;");
            asm volatile("cp.async.wait_group 1;");
        } else {
            asm volatile("cp.async.wait_group 0;");
        }
        __syncthreads();

        const int st = kc & 1;
        const int abase = st * GSTAGE;

#pragma unroll
        for (int ks = 0; ks < 2; ks++) {
            uint32_t aH[2][4], aL[2][4], bH[8][2], bL[8][2];
#pragma unroll
            for (int mt = 0; mt < 2; mt++) {
                uint32_t ad = sbase +
                    (uint32_t)(abase + (wm * 32 + mt * 16 + a_r) * GKP + ks * 16 + a_k) * 2;
                LDSM4(aH[mt][0], aH[mt][1], aH[mt][2], aH[mt][3], ad);
                ad += (uint32_t)(GBM * GKP) * 2;
                LDSM4(aL[mt][0], aL[mt][1], aL[mt][2], aL[mt][3], ad);
            }
#pragma unroll
            for (int p = 0; p < 4; p++) {
                uint32_t bd = sbase +
                    (uint32_t)(abase + 2 * GBM * GKP + (wn * 64 + p * 16 + b_r) * GKP + ks * 16 + b_k) * 2;
                LDSM4(bH[2 * p][0], bH[2 * p][1], bH[2 * p + 1][0], bH[2 * p + 1][1], bd);
                bd += (uint32_t)(GBM * GKP) * 2;
                LDSM4(bL[2 * p][0], bL[2 * p][1], bL[2 * p + 1][0], bL[2 * p + 1][1], bd);
            }
#pragma unroll
            for (int mt = 0; mt < 2; mt++) {
#pragma unroll
                for (int nt = 0; nt < 8; nt++) {
                    MMA16816(acc[mt][nt], aH[mt], bH[nt]);
                    MMA16816(acc[mt][nt], aH[mt], bL[nt]);
                    MMA16816(acc[mt][nt], aL[mt], bH[nt]);
                }
            }
        }
        __syncthreads();
    }

    // ---- epilogue: add bias, write fp32 ----
#pragma unroll
    for (int mt = 0; mt < 2; mt++) {
        int row0 = brow + wm * 32 + mt * 16 + (lane >> 2);
#pragma unroll
        for (int nt = 0; nt < 8; nt++) {
            int col = bcol + wn * 64 + nt * 8 + ((lane & 3) << 1);
            float b0 = bias[col], b1 = bias[col + 1];
            float2 r0 = make_float2(acc[mt][nt][0] + b0, acc[mt][nt][1] + b1);
            float2 r1 = make_float2(acc[mt][nt][2] + b0, acc[mt][nt][3] + b1);
            *(float2*)(C + (size_t)row0 * N + col) = r0;
            *(float2*)(C + (size_t)(row0 + 8) * N + col) = r1;
        }
    }
}

// ---------------------------------------------------------------------------
// Flash attention (unchanged from round 1): one block per (q-tile 64, h, b).
// ---------------------------------------------------------------------------
__global__ __launch_bounds__(256) void attn_kernel(float* __restrict__ attn_out)
{
    extern __shared__ float smf[];
    float* Qt = smf;
    float* KV = smf + 64 * APAD;
    float* Ps = smf + 2 * 64 * APAD;

    const int tid = threadIdx.x;
    const int tx = tid & 15;
    const int ty = tid >> 4;
    const int qtile = blockIdx.x;
    const int h = blockIdx.y;
    const int b = blockIdx.z;

    const float* qbase = g_qkv + (size_t)b * SEQ * QKV_COLS + h * DHEAD;
    const float* kbase = qbase + INNER;
    const float* vbase = qbase + 2 * INNER;

#pragma unroll
    for (int it = 0; it < 4; it++) {
        int i = tid + it * 256;
        int row = i >> 4;
        int d4 = (i & 15) << 2;
        float4 v = *(const float4*)(qbase + (size_t)(qtile * 64 + row) * QKV_COLS + d4);
        Qt[(d4 + 0) * APAD + row] = v.x * ATT_SCALE;
        Qt[(d4 + 1) * APAD + row] = v.y * ATT_SCALE;
        Qt[(d4 + 2) * APAD + row] = v.z * ATT_SCALE;
        Qt[(d4 + 3) * APAD + row] = v.w * ATT_SCALE;
    }

    float O[4][4] = {};
    float m[4] = {-1e30f, -1e30f, -1e30f, -1e30f};
    float l[4] = {};

    for (int t = 0; t < SEQ / 64; t++) {
#pragma unroll
        for (int it = 0; it < 4; it++) {
            int i = tid + it * 256;
            int col = i >> 4;
            int d4 = (i & 15) << 2;
            float4 v = *(const float4*)(kbase + (size_t)(t * 64 + col) * QKV_COLS + d4);
            KV[(d4 + 0) * APAD + col] = v.x;
            KV[(d4 + 1) * APAD + col] = v.y;
            KV[(d4 + 2) * APAD + col] = v.z;
            KV[(d4 + 3) * APAD + col] = v.w;
        }
        __syncthreads();

        float s00 = 0.f, s01 = 0.f, s02 = 0.f, s03 = 0.f;
        float s10 = 0.f, s11 = 0.f, s12 = 0.f, s13 = 0.f;
        float s20 = 0.f, s21 = 0.f, s22 = 0.f, s23 = 0.f;
        float s30 = 0.f, s31 = 0.f, s32 = 0.f, s33 = 0.f;
#pragma unroll 8
        for (int d = 0; d < 64; d++) {
            float4 a = *(const float4*)&Qt[d * APAD + ty * 4];
            float4 bb = *(const float4*)&KV[d * APAD + tx * 4];
            s00 += a.x * bb.x; s01 += a.x * bb.y; s02 += a.x * bb.z; s03 += a.x * bb.w;
            s10 += a.y * bb.x; s11 += a.y * bb.y; s12 += a.y * bb.z; s13 += a.y * bb.w;
            s20 += a.z * bb.x; s21 += a.z * bb.y; s22 += a.z * bb.z; s23 += a.z * bb.w;
            s30 += a.w * bb.x; s31 += a.w * bb.y; s32 += a.w * bb.z; s33 += a.w * bb.w;
        }
        __syncthreads();

#pragma unroll
        for (int it = 0; it < 4; it++) {
            int i = tid + it * 256;
            int kk = i >> 4;
            int d4 = (i & 15) << 2;
            *(float4*)&KV[kk * APAD + d4] =
                *(const float4*)(vbase + (size_t)(t * 64 + kk) * QKV_COLS + d4);
        }

        float sr[4][4] = {
            {s00, s01, s02, s03}, {s10, s11, s12, s13},
            {s20, s21, s22, s23}, {s30, s31, s32, s33}};
#pragma unroll
        for (int i = 0; i < 4; i++) {
            float tmax = fmaxf(fmaxf(sr[i][0], sr[i][1]), fmaxf(sr[i][2], sr[i][3]));
            tmax = fmaxf(tmax, __shfl_xor_sync(0xffffffffu, tmax, 8));
            tmax = fmaxf(tmax, __shfl_xor_sync(0xffffffffu, tmax, 4));
            tmax = fmaxf(tmax, __shfl_xor_sync(0xffffffffu, tmax, 2));
            tmax = fmaxf(tmax, __shfl_xor_sync(0xffffffffu, tmax, 1));
            float mn = fmaxf(m[i], tmax);
            float corr = __expf(m[i] - mn);
            m[i] = mn;
            float p0 = __expf(sr[i][0] - mn);
            float p1 = __expf(sr[i][1] - mn);
            float p2 = __expf(sr[i][2] - mn);
            float p3 = __expf(sr[i][3] - mn);
            float ls = p0 + p1 + p2 + p3;
            ls += __shfl_xor_sync(0xffffffffu, ls, 8);
            ls += __shfl_xor_sync(0xffffffffu, ls, 4);
            ls += __shfl_xor_sync(0xffffffffu, ls, 2);
            ls += __shfl_xor_sync(0xffffffffu, ls, 1);
            l[i] = l[i] * corr + ls;
            O[i][0] *= corr; O[i][1] *= corr; O[i][2] *= corr; O[i][3] *= corr;
            *(float4*)&Ps[(ty * 4 + i) * APAD + tx * 4] = make_float4(p0, p1, p2, p3);
        }
        __syncthreads();

#pragma unroll 4
        for (int kk = 0; kk < 64; kk++) {
            float4 vv = *(const float4*)&KV[kk * APAD + tx * 4];
#pragma unroll
            for (int i = 0; i < 4; i++) {
                float p = Ps[(ty * 4 + i) * APAD + kk];
                O[i][0] += p * vv.x;
                O[i][1] += p * vv.y;
                O[i][2] += p * vv.z;
                O[i][3] += p * vv.w;
            }
        }
        __syncthreads();
    }

#pragma unroll
    for (int i = 0; i < 4; i++) {
        float inv = 1.0f / l[i];
        float4 o = make_float4(O[i][0] * inv, O[i][1] * inv, O[i][2] * inv, O[i][3] * inv);
        size_t row = (size_t)b * SEQ + qtile * 64 + ty * 4 + i;
        *(float4*)(attn_out + row * INNER + h * DHEAD + tx * 4) = o;
    }
}

// ---------------------------------------------------------------------------
extern "C" void kernel_launch(void* const* d_in, const int* in_sizes, int n_in,
                              void* d_out, int out_size)
{
    const float* x     = (const float*)d_in[0];
    const float* w_qkv = (const float*)d_in[1];
    const float* b_qkv = (const float*)d_in[2];
    const float* w_out = (const float*)d_in[3];
    const float* b_out = (const float*)d_in[4];
    float* out = (float*)d_out;

    float *qkv = nullptr, *attn = nullptr;
    __nv_bfloat16 *xh, *xl, *ath, *atl, *wqh, *wql, *woh, *wol;
    cudaGetSymbolAddress((void**)&qkv, g_qkv);
    cudaGetSymbolAddress((void**)&attn, g_attn);
    cudaGetSymbolAddress((void**)&xh, g_xh);
    cudaGetSymbolAddress((void**)&xl, g_xl);
    cudaGetSymbolAddress((void**)&ath, g_ath);
    cudaGetSymbolAddress((void**)&atl, g_atl);
    cudaGetSymbolAddress((void**)&wqh, g_wqkvh);
    cudaGetSymbolAddress((void**)&wql, g_wqkvl);
    cudaGetSymbolAddress((void**)&woh, g_wouth);
    cudaGetSymbolAddress((void**)&wol, g_woutl);

    const int attn_smem = 3 * 64 * APAD * (int)sizeof(float);
    cudaFuncSetAttribute(attn_kernel, cudaFuncAttributeMaxDynamicSharedMemorySize, attn_smem);
    cudaFuncSetAttribute(gemm_bf16x3, cudaFuncAttributeMaxDynamicSharedMemorySize, GSMEM);

    // 0) precision splits + weight transposes
    split_f32<<<(ROWS * DIM / 4 + 255) / 256, 256>>>(x, xh, xl, ROWS * DIM / 4);
    transpose_split<<<dim3(QKV_COLS / 32, DIM / 32), dim3(32, 8)>>>(w_qkv, wqh, wql, DIM, QKV_COLS);
    transpose_split<<<dim3(DIM / 32, INNER / 32), dim3(32, 8)>>>(w_out, woh, wol, INNER, DIM);

    // 1) qkv = x @ w_qkv + b_qkv   (bf16x3 tensor cores, fp32 out)
    gemm_bf16x3<<<dim3(QKV_COLS / GBN, ROWS / GBM), 256, GSMEM>>>(
        xh, xl, wqh, wql, b_qkv, qkv, ROWS, QKV_COLS, DIM);

    // 2) flash attention -> g_attn
    attn_kernel<<<dim3(SEQ / 64, HEADS, BATCH), 256, attn_smem>>>(attn);

    // 3) split attn, then out = attn @ w_out + b_out
    split_f32<<<(ROWS * INNER / 4 + 255) / 256, 256>>>(attn, ath, atl, ROWS * INNER / 4);
    gemm_bf16x3<<<dim3(DIM / GBN, ROWS / GBM), 256, GSMEM>>>(
        ath, atl, woh, wol, b_out, out, ROWS, DIM, INNER);
}

// round 3
// speedup vs baseline: 2.7939x; 2.1286x over previous
#include <cuda_runtime.h>
#include <cuda_bf16.h>
#include <cstdint>

#define BATCH 4
#define SEQ 2048
#define DIM 1024
#define HEADS 16
#define DHEAD 64
#define INNER 1024
#define ROWS (BATCH * SEQ)      /* 8192 */
#define QKV_COLS (3 * INNER)    /* 3072 */
#define ATT_SCALE 0.125f

// ---------------- scratch (device globals) ----------------------------------
__device__ __nv_bfloat16 g_xh[(size_t)ROWS * DIM];
__device__ __nv_bfloat16 g_xl[(size_t)ROWS * DIM];
__device__ __nv_bfloat16 g_qkvh[(size_t)ROWS * QKV_COLS];
__device__ __nv_bfloat16 g_qkvl[(size_t)ROWS * QKV_COLS];
__device__ __nv_bfloat16 g_oh[(size_t)ROWS * INNER];
__device__ __nv_bfloat16 g_ol[(size_t)ROWS * INNER];
__device__ __nv_bfloat16 g_wqkvh[(size_t)QKV_COLS * DIM];  // [N][K]
__device__ __nv_bfloat16 g_wqkvl[(size_t)QKV_COLS * DIM];
__device__ __nv_bfloat16 g_wouth[(size_t)DIM * INNER];     // [N][K]
__device__ __nv_bfloat16 g_woutl[(size_t)DIM * INNER];

// ---------------------------------------------------------------------------
__device__ __forceinline__ uint32_t pack_bf16(float f0, float f1) {
    __nv_bfloat16 h0 = __float2bfloat16(f0), h1 = __float2bfloat16(f1);
    return (uint32_t)__bfloat16_as_ushort(h0) |
           ((uint32_t)__bfloat16_as_ushort(h1) << 16);
}
__device__ __forceinline__ void split_pack(float f0, float f1,
                                           uint32_t& hi, uint32_t& lo) {
    __nv_bfloat16 h0 = __float2bfloat16(f0), h1 = __float2bfloat16(f1);
    float r0 = f0 - __bfloat162float(h0), r1 = f1 - __bfloat162float(h1);
    hi = (uint32_t)__bfloat16_as_ushort(h0) |
         ((uint32_t)__bfloat16_as_ushort(h1) << 16);
    lo = (uint32_t)__bfloat16_as_ushort(__float2bfloat16(r0)) |
         ((uint32_t)__bfloat16_as_ushort(__float2bfloat16(r1)) << 16);
}

// ---------------------------------------------------------------------------
__global__ void split_f32(const float* __restrict__ in,
                          __nv_bfloat16* __restrict__ hi,
                          __nv_bfloat16* __restrict__ lo, int n4)
{
    int i = blockIdx.x * blockDim.x + threadIdx.x;
    if (i >= n4) return;
    float4 v = ((const float4*)in)[i];
    uint32_t h0, l0, h1, l1;
    split_pack(v.x, v.y, h0, l0);
    split_pack(v.z, v.w, h1, l1);
    ((uint2*)hi)[i] = make_uint2(h0, h1);
    ((uint2*)lo)[i] = make_uint2(l0, l1);
}

__global__ void transpose_split(const float* __restrict__ W,
                                __nv_bfloat16* __restrict__ Th,
                                __nv_bfloat16* __restrict__ Tl, int K, int N)
{
    __shared__ float t[32][33];
    int k0 = blockIdx.y * 32, n0 = blockIdx.x * 32;
    int tx = threadIdx.x, ty = threadIdx.y;
#pragma unroll
    for (int j = 0; j < 4; j++)
        t[ty + j * 8][tx] = W[(size_t)(k0 + ty + j * 8) * N + n0 + tx];
    __syncthreads();
#pragma unroll
    for (int j = 0; j < 4; j++) {
        float f = t[tx][ty + j * 8];
        __nv_bfloat16 h = __float2bfloat16(f);
        __nv_bfloat16 l = __float2bfloat16(f - __bfloat162float(h));
        size_t o = (size_t)(n0 + ty + j * 8) * K + k0 + tx;
        Th[o] = h;
        Tl[o] = l;
    }
}

// ---------------------------------------------------------------------------
// MMA / ldmatrix primitives
// ---------------------------------------------------------------------------
#define LDSM4(r0, r1, r2, r3, addr)                                          \
    asm volatile("ldmatrix.sync.aligned.m8n8.x4.shared.b16 {%0,%1,%2,%3}, [%4];" \
                 : "=r"(r0), "=r"(r1), "=r"(r2), "=r"(r3) : "r"(addr))
#define LDSM4T(r0, r1, r2, r3, addr)                                         \
    asm volatile("ldmatrix.sync.aligned.m8n8.x4.trans.shared.b16 {%0,%1,%2,%3}, [%4];" \
                 : "=r"(r0), "=r"(r1), "=r"(r2), "=r"(r3) : "r"(addr))
#define MMA16816(d, a, b)                                                    \
    asm volatile("mma.sync.aligned.m16n8k16.row.col.f32.bf16.bf16.f32 "      \
                 "{%0,%1,%2,%3},{%4,%5,%6,%7},{%8,%9},{%0,%1,%2,%3};"        \
                 : "+f"(d[0]), "+f"(d[1]), "+f"(d[2]), "+f"(d[3])            \
                 : "r"(a[0]), "r"(a[1]), "r"(a[2]), "r"(a[3]),               \
                   "r"(b[0]), "r"(b[1]))
#define MMAS(d, a0, a1, a2, a3, b0, b1)                                      \
    asm volatile("mma.sync.aligned.m16n8k16.row.col.f32.bf16.bf16.f32 "      \
                 "{%0,%1,%2,%3},{%4,%5,%6,%7},{%8,%9},{%0,%1,%2,%3};"        \
                 : "+f"(d[0]), "+f"(d[1]), "+f"(d[2]), "+f"(d[3])            \
                 : "r"(a0), "r"(a1), "r"(a2), "r"(a3), "r"(b0), "r"(b1))
#define CPASYNC16(dst, src)                                                  \
    asm volatile("cp.async.cg.shared.global [%0], [%1], 16;" :: "r"(dst), "l"(src))

// ---------------------------------------------------------------------------
// bf16x3 GEMM: C = (Ah+Al)[M,K] @ (Bh+Bl)^T([N][K]) + bias
// SPLIT_OUT: write bf16 hi/lo instead of fp32.
// ---------------------------------------------------------------------------
#define GBM 128
#define GBN 128
#define GBK 32
#define GKP 40
#define GSTAGE (4 * GBM * GKP)
#define GSMEM (2 * GSTAGE * 2)

template <bool SPLIT_OUT>
__global__ __launch_bounds__(256, 1) void gemm_bf16x3(
    const __nv_bfloat16* __restrict__ Ah, const __nv_bfloat16* __restrict__ Al,
    const __nv_bfloat16* __restrict__ Bh, const __nv_bfloat16* __restrict__ Bl,
    const float* __restrict__ bias, float* __restrict__ C,
    __nv_bfloat16* __restrict__ Chi, __nv_bfloat16* __restrict__ Clo,
    int M, int N, int K)
{
    extern __shared__ __nv_bfloat16 sm[];
    const int tid = threadIdx.x;
    const int lane = tid & 31, warp = tid >> 5;
    const int wm = warp >> 1, wn = warp & 1;
    const int brow = blockIdx.y * GBM, bcol = blockIdx.x * GBN;

    uint32_t sbase = (uint32_t)__cvta_generic_to_shared(sm);
    const int lrow = tid >> 2;
    const int lk = (tid & 3) << 3;

    const __nv_bfloat16* gA[2] = {Ah, Al};
    const __nv_bfloat16* gB[2] = {Bh, Bl};
    float acc[2][8][4] = {};

    const int a_r = lane & 15;
    const int a_k = (lane >> 4) << 3;
    const int bg = lane >> 3;
    const int b_r = ((bg & 2) << 2) + (lane & 7);
    const int b_k = (bg & 1) << 3;
    const int NK = K / GBK;

    auto load_stage = [&](int st, int k0) {
        int base = st * GSTAGE;
#pragma unroll
        for (int v = 0; v < 2; v++) {
#pragma unroll
            for (int i = 0; i < 2; i++) {
                int row = lrow + i * 64;
                uint32_t da = sbase + (uint32_t)(base + v * GBM * GKP + row * GKP + lk) * 2;
                CPASYNC16(da, gA[v] + (size_t)(brow + row) * K + k0 + lk);
                uint32_t db = sbase + (uint32_t)(base + (2 + v) * GBM * GKP + row * GKP + lk) * 2;
                CPASYNC16(db, gB[v] + (size_t)(bcol + row) * K + k0 + lk);
            }
        }
    };

    load_stage(0, 0);
    asm volatile("cp.async.commit_group;");

    for (int kc = 0; kc < NK; kc++) {
        if (kc + 1 < NK) {
            load_stage((kc + 1) & 1, (kc + 1) * GBK);
            asm volatile("cp.async.commit_group;");
            asm volatile("cp.async.wait_group 1;");
        } else {
            asm volatile("cp.async.wait_group 0;");
        }
        __syncthreads();

        const int abase = (kc & 1) * GSTAGE;
#pragma unroll
        for (int ks = 0; ks < 2; ks++) {
            uint32_t aH[2][4], aL[2][4], bH[8][2], bL[8][2];
#pragma unroll
            for (int mt = 0; mt < 2; mt++) {
                uint32_t ad = sbase +
                    (uint32_t)(abase + (wm * 32 + mt * 16 + a_r) * GKP + ks * 16 + a_k) * 2;
                LDSM4(aH[mt][0], aH[mt][1], aH[mt][2], aH[mt][3], ad);
                ad += (uint32_t)(GBM * GKP) * 2;
                LDSM4(aL[mt][0], aL[mt][1], aL[mt][2], aL[mt][3], ad);
            }
#pragma unroll
            for (int p = 0; p < 4; p++) {
                uint32_t bd = sbase +
                    (uint32_t)(abase + 2 * GBM * GKP + (wn * 64 + p * 16 + b_r) * GKP + ks * 16 + b_k) * 2;
                LDSM4(bH[2 * p][0], bH[2 * p][1], bH[2 * p + 1][0], bH[2 * p + 1][1], bd);
                bd += (uint32_t)(GBM * GKP) * 2;
                LDSM4(bL[2 * p][0], bL[2 * p][1], bL[2 * p + 1][0], bL[2 * p + 1][1], bd);
            }
#pragma unroll
            for (int mt = 0; mt < 2; mt++)
#pragma unroll
                for (int nt = 0; nt < 8; nt++) {
                    MMA16816(acc[mt][nt], aH[mt], bH[nt]);
                    MMA16816(acc[mt][nt], aH[mt], bL[nt]);
                    MMA16816(acc[mt][nt], aL[mt], bH[nt]);
                }
        }
        __syncthreads();
    }

#pragma unroll
    for (int mt = 0; mt < 2; mt++) {
        int row0 = brow + wm * 32 + mt * 16 + (lane >> 2);
#pragma unroll
        for (int nt = 0; nt < 8; nt++) {
            int col = bcol + wn * 64 + nt * 8 + ((lane & 3) << 1);
            float b0 = bias[col], b1 = bias[col + 1];
            float v00 = acc[mt][nt][0] + b0, v01 = acc[mt][nt][1] + b1;
            float v10 = acc[mt][nt][2] + b0, v11 = acc[mt][nt][3] + b1;
            if (SPLIT_OUT) {
                uint32_t hi, lo;
                size_t o0 = ((size_t)row0 * N + col) >> 1;
                size_t o1 = ((size_t)(row0 + 8) * N + col) >> 1;
                split_pack(v00, v01, hi, lo);
                ((uint32_t*)Chi)[o0] = hi;
                ((uint32_t*)Clo)[o0] = lo;
                split_pack(v10, v11, hi, lo);
                ((uint32_t*)Chi)[o1] = hi;
                ((uint32_t*)Clo)[o1] = lo;
            } else {
                *(float2*)(C + (size_t)row0 * N + col) = make_float2(v00, v01);
                *(float2*)(C + (size_t)(row0 + 8) * N + col) = make_float2(v10, v11);
            }
        }
    }
}

// ---------------------------------------------------------------------------
// Tensor-core flash attention (bf16x3), 128 q-rows per CTA, 64-key KV tiles.
// 8 warps x 16 q-rows. S acc reused as P fragments (FA2). Writes bf16 hi/lo.
// ---------------------------------------------------------------------------
#define TQ 128
#define TK 64
#define PR 72                       /* padded row, bf16 elems */
#define QELE (TQ * PR)              /* 9216  */
#define STG_ELE (4 * TK * PR)       /* 18432 */
#define ASMEM ((2 * QELE + 2 * STG_ELE) * 2)  /* 110592 B */

__global__ __launch_bounds__(256, 2) void attn_tc(
    const __nv_bfloat16* __restrict__ qkvh,
    const __nv_bfloat16* __restrict__ qkvl,
    __nv_bfloat16* __restrict__ outh,
    __nv_bfloat16* __restrict__ outl)
{
    extern __shared__ __nv_bfloat16 as[];
    const int tid = threadIdx.x;
    const int lane = tid & 31, warp = tid >> 5;
    const int qt = blockIdx.x, h = blockIdx.y, b = blockIdx.z;

    uint32_t sbase = (uint32_t)__cvta_generic_to_shared(as);

    // ldmatrix thread offsets (same mapping as validated gemm)
    const int a_r = lane & 15;
    const int a_k = (lane >> 4) << 3;
    const int bg = lane >> 3;
    const int b_r = ((bg & 2) << 2) + (lane & 7);
    const int b_k = (bg & 1) << 3;
    const int tb_k = ((bg & 1) << 3) + (lane & 7);   // trans: key row
    const int tb_n = (bg & 2) << 2;                  // trans: d col 0/8

    const size_t qrow0 = ((size_t)b * SEQ + (size_t)qt * TQ);

    // ---- load Q (hi/lo), 4 chunks of 16B per thread per matrix ----
    {
        const __nv_bfloat16* src[2] = {qkvh, qkvl};
#pragma unroll
        for (int v = 0; v < 2; v++)
#pragma unroll
            for (int i = 0; i < 4; i++) {
                int c = i * 256 + tid;
                int row = c >> 3, col8 = (c & 7) << 3;
                uint32_t dst = sbase + (uint32_t)(v * QELE + row * PR + col8) * 2;
                CPASYNC16(dst, src[v] + (qrow0 + row) * QKV_COLS + h * DHEAD + col8);
            }
    }

    auto load_kv = [&](int st, int t) {
        const __nv_bfloat16* src[2] = {qkvh, qkvl};
        size_t krow0 = (size_t)b * SEQ + (size_t)t * TK;
#pragma unroll
        for (int m = 0; m < 4; m++) {           // Kh,Kl,Vh,Vl
            int gofs = (m < 2 ? INNER : 2 * INNER) + h * DHEAD;
            const __nv_bfloat16* s = src[m & 1];
#pragma unroll
            for (int i = 0; i < 2; i++) {
                int c = i * 256 + tid;
                int row = c >> 3, col8 = (c & 7) << 3;
                uint32_t dst = sbase +
                    (uint32_t)(2 * QELE + st * STG_ELE + m * TK * PR + row * PR + col8) * 2;
                CPASYNC16(dst, s + (krow0 + row) * QKV_COLS + gofs + col8);
            }
        }
    };

    load_kv(0, 0);
    asm volatile("cp.async.commit_group;");

    float acc_o[8][4] = {};
    float mrow[2] = {-1e30f, -1e30f};
    float lrow[2] = {0.f, 0.f};

    const int NT = SEQ / TK;  // 32
    for (int t = 0; t < NT; t++) {
        if (t + 1 < NT) {
            load_kv((t + 1) & 1, t + 1);
            asm volatile("cp.async.commit_group;");
            asm volatile("cp.async.wait_group 1;");
        } else {
            asm volatile("cp.async.wait_group 0;");
        }
        __syncthreads();

        const int kb = 2 * QELE + (t & 1) * STG_ELE;

        // ---- S = Qh Kh + Qh Kl + Ql Kh ----
        float acc_s[8][4] = {};
#pragma unroll
        for (int ks = 0; ks < 4; ks++) {
            uint32_t aH[4], aL[4];
            uint32_t ad = sbase + (uint32_t)((warp * 16 + a_r) * PR + ks * 16 + a_k) * 2;
            LDSM4(aH[0], aH[1], aH[2], aH[3], ad);
            LDSM4(aL[0], aL[1], aL[2], aL[3], ad + (uint32_t)QELE * 2);
#pragma unroll
            for (int p = 0; p < 4; p++) {
                uint32_t h0, h1, h2, h3, l0, l1, l2, l3;
                uint32_t bd = sbase +
                    (uint32_t)(kb + (p * 16 + b_r) * PR + ks * 16 + b_k) * 2;
                LDSM4(h0, h1, h2, h3, bd);
                LDSM4(l0, l1, l2, l3, bd + (uint32_t)(TK * PR) * 2);
                MMAS(acc_s[2 * p], aH[0], aH[1], aH[2], aH[3], h0, h1);
                MMAS(acc_s[2 * p], aH[0], aH[1], aH[2], aH[3], l0, l1);
                MMAS(acc_s[2 * p], aL[0], aL[1], aL[2], aL[3], h0, h1);
                MMAS(acc_s[2 * p + 1], aH[0], aH[1], aH[2], aH[3], h2, h3);
                MMAS(acc_s[2 * p + 1], aH[0], aH[1], aH[2], aH[3], l2, l3);
                MMAS(acc_s[2 * p + 1], aL[0], aL[1], aL[2], aL[3], h2, h3);
            }
        }

        // ---- online softmax (rows g = lane>>2 and g+8) ----
#pragma unroll
        for (int nt = 0; nt < 8; nt++)
#pragma unroll
            for (int j = 0; j < 4; j++) acc_s[nt][j] *= ATT_SCALE;

#pragma unroll
        for (int r = 0; r < 2; r++) {
            float mx = -1e30f;
#pragma unroll
            for (int nt = 0; nt < 8; nt++)
                mx = fmaxf(mx, fmaxf(acc_s[nt][2 * r], acc_s[nt][2 * r + 1]));
            mx = fmaxf(mx, __shfl_xor_sync(0xffffffffu, mx, 1));
            mx = fmaxf(mx, __shfl_xor_sync(0xffffffffu, mx, 2));
            float mn = fmaxf(mrow[r], mx);
            float corr = __expf(mrow[r] - mn);
            mrow[r] = mn;
            float sum = 0.f;
#pragma unroll
            for (int nt = 0; nt < 8; nt++) {
                float p0 = __expf(acc_s[nt][2 * r] - mn);
                float p1 = __expf(acc_s[nt][2 * r + 1] - mn);
                acc_s[nt][2 * r] = p0;
                acc_s[nt][2 * r + 1] = p1;
                sum += p0 + p1;
            }
            sum += __shfl_xor_sync(0xffffffffu, sum, 1);
            sum += __shfl_xor_sync(0xffffffffu, sum, 2);
            lrow[r] = lrow[r] * corr + sum;
#pragma unroll
            for (int nt = 0; nt < 8; nt++) {
                acc_o[nt][2 * r] *= corr;
                acc_o[nt][2 * r + 1] *= corr;
            }
        }

        // ---- O += (Ph + Pl) @ (Vh + Vl)  (3 terms) ----
        const int vb = kb + 2 * TK * PR;
#pragma unroll
        for (int kc = 0; kc < 4; kc++) {
            uint32_t aPh[4], aPl[4];
#pragma unroll
            for (int j = 0; j < 4; j++) {
                int tile = 2 * kc + (j >> 1);
                int c0 = (j & 1) << 1;
                split_pack(acc_s[tile][c0], acc_s[tile][c0 + 1], aPh[j], aPl[j]);
            }
#pragma unroll
            for (int p = 0; p < 4; p++) {
                uint32_t h0, h1, h2, h3, l0, l1, l2, l3;
                uint32_t vd = sbase +
                    (uint32_t)(vb + (kc * 16 + tb_k) * PR + p * 16 + tb_n) * 2;
                LDSM4T(h0, h1, h2, h3, vd);
                LDSM4T(l0, l1, l2, l3, vd + (uint32_t)(TK * PR) * 2);
                MMAS(acc_o[2 * p], aPh[0], aPh[1], aPh[2], aPh[3], h0, h1);
                MMAS(acc_o[2 * p], aPh[0], aPh[1], aPh[2], aPh[3], l0, l1);
                MMAS(acc_o[2 * p], aPl[0], aPl[1], aPl[2], aPl[3], h0, h1);
                MMAS(acc_o[2 * p + 1], aPh[0], aPh[1], aPh[2], aPh[3], h2, h3);
                MMAS(acc_o[2 * p + 1], aPh[0], aPh[1], aPh[2], aPh[3], l2, l3);
                MMAS(acc_o[2 * p + 1], aPl[0], aPl[1], aPl[2], aPl[3], h2, h3);
            }
        }
        __syncthreads();
    }

    // ---- epilogue: normalize, split to bf16 hi/lo, write [8192][1024] ----
    float inv0 = 1.0f / lrow[0], inv1 = 1.0f / lrow[1];
    size_t row0 = qrow0 + warp * 16 + (lane >> 2);
#pragma unroll
    for (int nt = 0; nt < 8; nt++) {
        int col = h * DHEAD + nt * 8 + ((lane & 3) << 1);
        uint32_t hi, lo;
        size_t o0 = (row0 * INNER + col) >> 1;
        size_t o1 = ((row0 + 8) * INNER + col) >> 1;
        split_pack(acc_o[nt][0] * inv0, acc_o[nt][1] * inv0, hi, lo);
        ((uint32_t*)outh)[o0] = hi;
        ((uint32_t*)outl)[o0] = lo;
        split_pack(acc_o[nt][2] * inv1, acc_o[nt][3] * inv1, hi, lo);
        ((uint32_t*)outh)[o1] = hi;
        ((uint32_t*)outl)[o1] = lo;
    }
}

// ---------------------------------------------------------------------------
extern "C" void kernel_launch(void* const* d_in, const int* in_sizes, int n_in,
                              void* d_out, int out_size)
{
    const float* x     = (const float*)d_in[0];
    const float* w_qkv = (const float*)d_in[1];
    const float* b_qkv = (const float*)d_in[2];
    const float* w_out = (const float*)d_in[3];
    const float* b_out = (const float*)d_in[4];
    float* out = (float*)d_out;

    __nv_bfloat16 *xh, *xl, *qh, *ql, *oh, *ol, *wqh, *wql, *woh, *wol;
    cudaGetSymbolAddress((void**)&xh, g_xh);
    cudaGetSymbolAddress((void**)&xl, g_xl);
    cudaGetSymbolAddress((void**)&qh, g_qkvh);
    cudaGetSymbolAddress((void**)&ql, g_qkvl);
    cudaGetSymbolAddress((void**)&oh, g_oh);
    cudaGetSymbolAddress((void**)&ol, g_ol);
    cudaGetSymbolAddress((void**)&wqh, g_wqkvh);
    cudaGetSymbolAddress((void**)&wql, g_wqkvl);
    cudaGetSymbolAddress((void**)&woh, g_wouth);
    cudaGetSymbolAddress((void**)&wol, g_woutl);

    cudaFuncSetAttribute(gemm_bf16x3<true>,
                         cudaFuncAttributeMaxDynamicSharedMemorySize, GSMEM);
    cudaFuncSetAttribute(gemm_bf16x3<false>,
                         cudaFuncAttributeMaxDynamicSharedMemorySize, GSMEM);
    cudaFuncSetAttribute(attn_tc,
                         cudaFuncAttributeMaxDynamicSharedMemorySize, ASMEM);

    // 0) input split + weight transposes
    split_f32<<<(ROWS * DIM / 4 + 255) / 256, 256>>>(x, xh, xl, ROWS * DIM / 4);
    transpose_split<<<dim3(QKV_COLS / 32, DIM / 32), dim3(32, 8)>>>(w_qkv, wqh, wql, DIM, QKV_COLS);
    transpose_split<<<dim3(DIM / 32, INNER / 32), dim3(32, 8)>>>(w_out, woh, wol, INNER, DIM);

    // 1) qkv = x @ w_qkv + b_qkv  -> bf16 hi/lo directly
    gemm_bf16x3<true><<<dim3(QKV_COLS / GBN, ROWS / GBM), 256, GSMEM>>>(
        xh, xl, wqh, wql, b_qkv, nullptr, qh, ql, ROWS, QKV_COLS, DIM);

    // 2) tensor-core flash attention -> bf16 hi/lo [b n (h d)]
    attn_tc<<<dim3(SEQ / TQ, HEADS, BATCH), 256, ASMEM>>>(qh, ql, oh, ol);

    // 3) out = attn @ w_out + b_out (fp32)
    gemm_bf16x3<false><<<dim3(DIM / GBN, ROWS / GBM), 256, GSMEM>>>(
        oh, ol, woh, wol, b_out, out, nullptr, nullptr, ROWS, DIM, INNER);
}